// round 11
// baseline (speedup 1.0000x reference)
#include <cuda_runtime.h>

#define BN    32768      // B*N
#define NPTS  8192
#define KNN   16
#define BINS  4096
#define XLO   (-6.0f)
#define BSCALE (BINS / 12.0f)          // bins over [-6, 6]
#define DELTA  (12.0f / BINS)
#define MARGIN 1e-3f

typedef unsigned long long ull;

__device__ float4 g_pts[BN];           // (x,y,z,sq) original order
__device__ int    g_hist[4 * BINS];
__device__ int    g_off [4 * BINS];
__device__ float4 g_sx  [BN];          // scattered (bin-ordered) points
__device__ int    g_sidx[BN];          // orig index per scattered pos
__device__ ulonglong2 g_ta[BN / 2];    // pair-packed (x-pair, y-pair)
__device__ ulonglong2 g_tb[BN / 2];    // pair-packed (z-pair, w-pair)
__device__ int    g_idx[BN * KNN];
__device__ float  g_lt[(size_t)BN * 192];

// ---- packed f32x2 helpers (each lane independent exact fp32) --------------
__device__ __forceinline__ ull pk(float a, float b) {
    ull r; asm("mov.b64 %0, {%1,%2};" : "=l"(r) : "f"(a), "f"(b)); return r;
}
__device__ __forceinline__ void upk(ull v, float& a, float& b) {
    asm("mov.b64 {%0,%1}, %2;" : "=f"(a), "=f"(b) : "l"(v));
}
__device__ __forceinline__ ull fma2(ull a, ull b, ull c) {
    ull r; asm("fma.rn.f32x2 %0, %1, %2, %3;" : "=l"(r) : "l"(a), "l"(b), "l"(c)); return r;
}
__device__ __forceinline__ ull mul2(ull a, ull b) {
    ull r; asm("mul.rn.f32x2 %0, %1, %2;" : "=l"(r) : "l"(a), "l"(b)); return r;
}
__device__ __forceinline__ ull add2(ull a, ull b) {
    ull r; asm("add.rn.f32x2 %0, %1, %2;" : "=l"(r) : "l"(a), "l"(b)); return r;
}

// monotone order-preserving float -> u32 (standard radix trick)
__device__ __forceinline__ unsigned fmap(float f) {
    unsigned b = __float_as_uint(f);
    return b ^ ((unsigned)((int)b >> 31) | 0x80000000u);
}

// shared bin function — MUST be identical in pack/scatter/knn (same fp expr)
__device__ __forceinline__ int binof(float x) {
    int b = (int)((x - XLO) * BSCALE);
    return min(BINS - 1, max(0, b));
}

// sorted insert of u64 key into ascending 16-list (shift chain, no dyn index)
__device__ __forceinline__ void kins16(ull k, ull* B) {
    if (k >= B[15]) return;
    bool cs = true;
#pragma unroll
    for (int s = 15; s > 0; --s) {
        bool cp = k < B[s - 1];
        ull nb = cp ? B[s - 1] : (cs ? k : B[s]);
        B[s] = nb;
        cs = cp;
    }
    if (cs) B[0] = k;
}

// ---------------------------------------------------------------------------
// 0. zero histogram (graph replays rerun everything, so zero each run)
// ---------------------------------------------------------------------------
__global__ void zero_kernel() {
    int i = blockIdx.x * 256 + threadIdx.x;
    g_hist[i] = 0;
}

// ---------------------------------------------------------------------------
// 1. pack (x,y,z, sq) + histogram. sq = ((x*x)+(y*y))+(z*z), each op
//    separately rounded (exact XLA replication -- LOAD-BEARING)
// ---------------------------------------------------------------------------
__global__ void pack_kernel(const float* __restrict__ xytp) {
    int i = blockIdx.x * blockDim.x + threadIdx.x;
    float4 p = ((const float4*)xytp)[i];
    float xx = __fmul_rn(p.x, p.x);
    float yy = __fmul_rn(p.y, p.y);
    float zz = __fmul_rn(p.z, p.z);
    p.w = __fadd_rn(__fadd_rn(xx, yy), zz);
    g_pts[i] = p;
    atomicAdd(&g_hist[(i >> 13) * BINS + binof(p.x)], 1);
}

// ---------------------------------------------------------------------------
// 2. exclusive scan of per-batch histogram (4096 bins, 1024 threads/batch)
// ---------------------------------------------------------------------------
__global__ void __launch_bounds__(1024) scan_kernel() {
    __shared__ int sv[1024];
    int b = blockIdx.x, t = threadIdx.x;
    int base = b * BINS + t * 4;
    int a0 = g_hist[base], a1 = g_hist[base + 1], a2 = g_hist[base + 2], a3 = g_hist[base + 3];
    int s = a0 + a1 + a2 + a3;
    sv[t] = s;
    __syncthreads();
    for (int off = 1; off < 1024; off <<= 1) {
        int v = (t >= off) ? sv[t - off] : 0;
        __syncthreads();
        sv[t] += v;
        __syncthreads();
    }
    int excl = sv[t] - s;
    g_off[base]     = excl;
    g_off[base + 1] = excl + a0;
    g_off[base + 2] = excl + a0 + a1;
    g_off[base + 3] = excl + a0 + a1 + a2;
}

// ---------------------------------------------------------------------------
// 3. scatter points into bin order (within-bin order arbitrary -- selection
//    is exact-set via lexicographic keys, so nondeterminism is harmless)
// ---------------------------------------------------------------------------
__global__ void scatter_kernel() {
    int i = blockIdx.x * blockDim.x + threadIdx.x;
    int b = i >> 13;
    float4 p = g_pts[i];
    int pos = atomicAdd(&g_off[b * BINS + binof(p.x)], 1);
    g_sx  [b * NPTS + pos] = p;
    g_sidx[b * NPTS + pos] = i & (NPTS - 1);
}

// ---------------------------------------------------------------------------
// 4. pair-pack scattered points for f32x2 distance math
// ---------------------------------------------------------------------------
__global__ void repack_kernel() {
    int j = blockIdx.x * blockDim.x + threadIdx.x;   // pair index, < BN/2
    float4 p0 = g_sx[2 * j];
    float4 p1 = g_sx[2 * j + 1];
    ulonglong2 va, vb;
    va.x = pk(p0.x, p1.x);  va.y = pk(p0.y, p1.y);
    vb.x = pk(p0.z, p1.z);  vb.y = pk(p0.w, p1.w);
    g_ta[j] = va;  g_tb[j] = vb;
}

// ---------------------------------------------------------------------------
// 5. windowed kNN. Warp pair per 32 consecutive bin-ordered queries:
//    dir 0 sweeps right from q0 (incl. the queries), dir 1 sweeps left.
//    Exact reference d2 per tested candidate; exact (d, idx) selection keys;
//    conservative bin-edge pruning with MARGIN >> fp noise.
// ---------------------------------------------------------------------------
__global__ void __launch_bounds__(256) knn_win_kernel() {
    __shared__ ull MS[8][32][KNN];     // 32KB: per-warp partial results
    int tid = threadIdx.x, warp = tid >> 5, lane = tid & 31;
    int b = blockIdx.y;
    int group = warp >> 1, dir = warp & 1;
    int q0 = (blockIdx.x * 4 + group) * 32;
    int p  = q0 + lane;

    const float4*     SX  = g_sx   + b * NPTS;
    const int*        SI  = g_sidx + b * NPTS;
    const ulonglong2* TA  = g_ta   + b * (NPTS / 2);
    const ulonglong2* TB  = g_tb   + b * (NPTS / 2);
    const int2*       SI2 = (const int2*)SI;

    float4 me = SX[p];
    int orig  = SI[p];
    ull m2x = pk(-2.0f * me.x, -2.0f * me.x);   // exact power-of-2 scale
    ull m2y = pk(-2.0f * me.y, -2.0f * me.y);
    ull m2z = pk(-2.0f * me.z, -2.0f * me.z);
    ull mw  = pk(me.w, me.w);

    ull B[KNN];
#pragma unroll
    for (int s = 0; s < KNN; s++) B[s] = ~0ULL;

    int pj0 = q0 >> 1;
    // ---- seed: 8 pairs (right: pj0..pj0+7 ; left: pj0-8..pj0-1) ----
#pragma unroll
    for (int s = 0; s < 8; s++) {
        int j = dir ? (pj0 - 8 + s) : (pj0 + s);
        bool v = (j >= 0) && (j < NPTS / 2);
        int jj = v ? j : 0;
        ulonglong2 A = TA[jj], Z = TB[jj];
        ull dn = fma2(m2z, Z.x, fma2(m2y, A.y, mul2(m2x, A.x)));
        ull dd = add2(add2(mw, Z.y), dn);
        float d0, d1; upk(dd, d0, d1);
        int2 ii = SI2[jj];
        if (v) {
            kins16((((ull)fmap(d0)) << 32) | (unsigned)ii.x, B);
            kins16((((ull)fmap(d1)) << 32) | (unsigned)ii.y, B);
        }
    }

    // ---- adaptive sweep, 4 pairs (8 candidates) per ballot ----
    int step = dir ? -1 : 1;
    int pj   = dir ? (pj0 - 9) : (pj0 + 8);
    while (true) {
        float xlast = 0.0f; bool vlast = false;
#pragma unroll
        for (int u = 0; u < 4; u++) {
            int j = pj + step * u;
            bool v = (j >= 0) && (j < NPTS / 2);
            int jj = v ? j : 0;
            ulonglong2 A = TA[jj], Z = TB[jj];
            // exact reference arithmetic (validated bitwise):
            ull dn = fma2(m2z, Z.x, fma2(m2y, A.y, mul2(m2x, A.x)));
            ull dd = add2(add2(mw, Z.y), dn);
            float d0, d1; upk(dd, d0, d1);
            int2 ii = SI2[jj];
            ull k0 = (((ull)fmap(d0)) << 32) | (unsigned)ii.x;
            ull k1 = (((ull)fmap(d1)) << 32) | (unsigned)ii.y;
            if (v && k0 < B[15]) kins16(k0, B);
            if (v && k1 < B[15]) kins16(k1, B);
            if (u == 3) {
                float x0, x1; upk(A.x, x0, x1);
                xlast = dir ? x0 : x1;       // outermost candidate's x
                vlast = v;
            }
        }
        // prune: no later candidate can beat exact B[15] (margin-safe)
        bool active;
        {
            unsigned fk = (unsigned)(B[15] >> 32);
            unsigned bits = ((int)fk < 0) ? (fk ^ 0x80000000u) : ~fk;
            float dmax = __uint_as_float(bits);     // +NaN while not full -> no prune
            int cb = binof(xlast);
            float bound = dir ? (me.x - (XLO + (cb + 1) * DELTA))   // left: me.x - bin_hi
                              : ((XLO + cb * DELTA) - me.x);        // right: bin_lo - me.x
            bool edge  = dir ? (cb >= BINS - 1) : (cb <= 0);        // clamped bins: no prune
            bool pruned = vlast && !edge && (bound > 0.0f) &&
                          (bound * bound > dmax + MARGIN);
            int jn = pj + step * 4;
            bool inrange = dir ? (jn >= 0) : (jn < NPTS / 2);
            active = inrange && !pruned;
        }
        if (!__ballot_sync(0xffffffffu, active)) break;
        pj += step * 4;
    }

    // ---- publish, merge L into R, write ----
#pragma unroll
    for (int s = 0; s < KNN; s++) MS[warp][lane][s] = B[s];
    __syncthreads();
    if (dir == 0) {
#pragma unroll
        for (int s = 0; s < KNN; s++) {
            ull k = MS[warp + 1][lane][s];
            if (k < B[15]) kins16(k, B);
        }
        int ob = (b * NPTS + orig) * KNN;
#pragma unroll
        for (int s = 0; s < KNN; s++)
            g_idx[ob + s] = (int)(unsigned)(B[s] & 0xffffffffu);
    }
}

// ---------------------------------------------------------------------------
// 6. lt = features @ lt_w + lt_b, f32x2 over k-pairs
// ---------------------------------------------------------------------------
__global__ void __launch_bounds__(256) lt_kernel(const float* __restrict__ feat,
                                                 const float* __restrict__ w,
                                                 const float* __restrict__ bias) {
    __shared__ __align__(16) float fs[32][64];
    int row0 = blockIdx.x * 32;
    for (int i = threadIdx.x; i < 32 * 64; i += 256)
        fs[i >> 6][i & 63] = feat[row0 * 64 + i];
    __syncthreads();

    int c = threadIdx.x;
    if (c < 192) {
        ull w2[32];
#pragma unroll
        for (int k = 0; k < 32; k++)
            w2[k] = pk(w[(2 * k) * 192 + c], w[(2 * k + 1) * 192 + c]);
        float bc = bias[c];
        for (int r = 0; r < 32; r++) {
            ull acc = pk(bc, 0.0f);
            const ull* fr = (const ull*)&fs[r][0];
#pragma unroll
            for (int k = 0; k < 32; k++)
                acc = fma2(fr[k], w2[k], acc);
            float ax, ay; upk(acc, ax, ay);
            g_lt[(size_t)(row0 + r) * 192 + c] = ax + ay;
        }
    }
}

// ---------------------------------------------------------------------------
// 7. fused: gather -> delta MLP -> LN -> softmax(k) -> output
//    (neighbor order is arbitrary: softmax+sum over k is permutation-invariant)
// ---------------------------------------------------------------------------
__global__ void __launch_bounds__(128) fused_kernel(
    const float* __restrict__ xytp,
    const float* __restrict__ pe_w1, const float* __restrict__ pe_b1,
    const float* __restrict__ pe_w2, const float* __restrict__ pe_b2,
    const float* __restrict__ ln_g,  const float* __restrict__ ln_b,
    float* __restrict__ out)
{
    __shared__ float  W2s[64 * 64];
    __shared__ float4 rels[4][16];
    __shared__ __align__(16) float HS[4][64][20];

    int tid = threadIdx.x, w = tid >> 5, lane = tid & 31;
    for (int i = tid; i < 4096; i += 128) W2s[i] = pe_w2[i];

    int pt = blockIdx.x * 4 + w;
    int b  = pt >> 13;
    int c0 = lane, c1 = lane + 32;

    float w1a[4], w1b[4];
#pragma unroll
    for (int d = 0; d < 4; d++) { w1a[d] = pe_w1[d * 64 + c0]; w1b[d] = pe_w1[d * 64 + c1]; }
    float b10 = pe_b1[c0], b11 = pe_b1[c1];
    float b20 = pe_b2[c0], b21 = pe_b2[c1];
    float g0  = ln_g[c0],  g1  = ln_g[c1];
    float q0  = ln_b[c0],  q1  = ln_b[c1];

    const int* idxp = g_idx + pt * KNN;
    float4 ctr = ((const float4*)xytp)[pt];
    if (lane < 16) {
        int nb = idxp[lane];
        float4 p = ((const float4*)xytp)[b * NPTS + nb];
        rels[w][lane] = make_float4(ctr.x - p.x, ctr.y - p.y, ctr.z - p.z, ctr.w - p.w);
    }
    __syncthreads();

#pragma unroll
    for (int k = 0; k < KNN; k++) {
        float4 r = rels[w][k];
        float h0 = fmaf(r.w, w1a[3], fmaf(r.z, w1a[2], fmaf(r.y, w1a[1], fmaf(r.x, w1a[0], b10))));
        float h1 = fmaf(r.w, w1b[3], fmaf(r.z, w1b[2], fmaf(r.y, w1b[1], fmaf(r.x, w1b[0], b11))));
        HS[w][c0][k] = fmaxf(h0, 0.f);
        HS[w][c1][k] = fmaxf(h1, 0.f);
    }
    __syncwarp();

    ull d0p[8], d1p[8];
#pragma unroll
    for (int m = 0; m < 8; m++) { d0p[m] = pk(b20, b20); d1p[m] = pk(b21, b21); }
#pragma unroll 4
    for (int j = 0; j < 64; j++) {
        ull wv0 = pk(W2s[j * 64 + c0], W2s[j * 64 + c0]);
        ull wv1 = pk(W2s[j * 64 + c1], W2s[j * 64 + c1]);
        const ulonglong2* hr = (const ulonglong2*)&HS[w][j][0];
        ulonglong2 ha = hr[0], hb = hr[1];
        ull hp[4] = { ha.x, ha.y, hb.x, hb.y };
#pragma unroll
        for (int m = 0; m < 4; m++) {
            d0p[m] = fma2(hp[m], wv0, d0p[m]);
            d1p[m] = fma2(hp[m], wv1, d1p[m]);
        }
        ulonglong2 hc = hr[2], hd = hr[3];
        ull hq[4] = { hc.x, hc.y, hd.x, hd.y };
#pragma unroll
        for (int m = 0; m < 4; m++) {
            d0p[m + 4] = fma2(hq[m], wv0, d0p[m + 4]);
            d1p[m + 4] = fma2(hq[m], wv1, d1p[m + 4]);
        }
    }
    float d0[KNN], d1[KNN];
#pragma unroll
    for (int m = 0; m < 8; m++) {
        upk(d0p[m], d0[2 * m], d0[2 * m + 1]);
        upk(d1p[m], d1[2 * m], d1[2 * m + 1]);
    }

    const float* ltb = g_lt + (size_t)(b * NPTS) * 192;
    int n = pt & (NPTS - 1);
    float vp0 = ltb[(size_t)n * 192 + c0];
    float vp1 = ltb[(size_t)n * 192 + c1];

    float a0[KNN], a1[KNN], p0[KNN], p1[KNN];
#pragma unroll
    for (int k = 0; k < KNN; k++) {
        int nb = idxp[k];
        const float* lr = ltb + (size_t)nb * 192;
        float ps0 = lr[64 + c0],  ps1 = lr[64 + c1];
        float al0 = lr[128 + c0], al1 = lr[128 + c1];
        float pr0 = (vp0 - ps0) + d0[k];
        float pr1 = (vp1 - ps1) + d1[k];
        a0[k] = al0 + d0[k];
        a1[k] = al1 + d1[k];
        float sm = pr0 + pr1;
        float sq = fmaf(pr0, pr0, pr1 * pr1);
#pragma unroll
        for (int off = 16; off > 0; off >>= 1) {
            sm += __shfl_xor_sync(0xffffffffu, sm, off);
            sq += __shfl_xor_sync(0xffffffffu, sq, off);
        }
        float mu  = sm * (1.0f / 64.0f);
        float var = fmaf(-mu, mu, sq * (1.0f / 64.0f));
        float rs  = rsqrtf(var + 1e-5f);
        p0[k] = fmaf((pr0 - mu) * rs, g0, q0) * 0.125f;
        p1[k] = fmaf((pr1 - mu) * rs, g1, q1) * 0.125f;
    }

    float m0 = -3.4e38f, m1 = -3.4e38f;
#pragma unroll
    for (int k = 0; k < KNN; k++) { m0 = fmaxf(m0, p0[k]); m1 = fmaxf(m1, p1[k]); }
    float z0 = 0.f, z1 = 0.f, o0 = 0.f, o1 = 0.f;
#pragma unroll
    for (int k = 0; k < KNN; k++) {
        float e0 = __expf(p0[k] - m0);
        float e1 = __expf(p1[k] - m1);
        z0 += e0; z1 += e1;
        o0 = fmaf(e0, a0[k], o0);
        o1 = fmaf(e1, a1[k], o1);
    }
    out[(size_t)pt * 64 + c0] = o0 / z0;
    out[(size_t)pt * 64 + c1] = o1 / z1;
}

// ---------------------------------------------------------------------------
extern "C" void kernel_launch(void* const* d_in, const int* in_sizes, int n_in,
                              void* d_out, int out_size) {
    const float* xytp     = (const float*)d_in[0];
    const float* features = (const float*)d_in[1];
    const float* pe_w1    = (const float*)d_in[2];
    const float* pe_b1    = (const float*)d_in[3];
    const float* pe_w2    = (const float*)d_in[4];
    const float* pe_b2    = (const float*)d_in[5];
    const float* lt_w     = (const float*)d_in[6];
    const float* lt_b     = (const float*)d_in[7];
    const float* ln_g     = (const float*)d_in[8];
    const float* ln_b     = (const float*)d_in[9];
    float* out = (float*)d_out;

    zero_kernel<<<(4 * BINS) / 256, 256>>>();
    pack_kernel<<<BN / 256, 256>>>(xytp);
    scan_kernel<<<4, 1024>>>();
    scatter_kernel<<<BN / 256, 256>>>();
    repack_kernel<<<(BN / 2) / 256, 256>>>();
    dim3 kg(NPTS / 128, 4);
    knn_win_kernel<<<kg, 256>>>();
    lt_kernel<<<BN / 32, 256>>>(features, lt_w, lt_b);
    fused_kernel<<<BN / 4, 128>>>(xytp, pe_w1, pe_b1, pe_w2, pe_b2, ln_g, ln_b, out);
}